// round 1
// baseline (speedup 1.0000x reference)
#include <cuda_runtime.h>

#define T_STEPS 512
#define HID     64
#define BATCH   2048
#define NB      16
#define NTHR    256

// Inter-layer scratch: full h1 sequence [B, T, H] fp32 (256 MB), plus last-h of layer 1.
__device__ float g_h1[(size_t)BATCH * T_STEPS * HID];
__device__ float g_h2[BATCH * HID];

typedef unsigned long long ull;

__device__ __forceinline__ ull pack2(float a, float b) {
    ull r; asm("mov.b64 %0, {%1,%2};" : "=l"(r) : "f"(a), "f"(b)); return r;
}
__device__ __forceinline__ void ffma2(ull &acc, ull a, ull b) {
    asm("fma.rn.f32x2 %0, %1, %2, %0;" : "+l"(acc) : "l"(a), "l"(b));
}
__device__ __forceinline__ void unpack2(ull v, float &lo, float &hi) {
    asm("mov.b64 {%0,%1}, %2;" : "=f"(lo), "=f"(hi) : "l"(v));
}

// sigmoid via fast exp (rel err ~2^-21, fine vs 1e-3 budget)
__device__ __forceinline__ float sigf(float x) {
    return __fdividef(1.f, 1.f + __expf(-x));
}
// tanh(x) = 2*sigmoid(2x) - 1 ; cancellation at small x is benign in absolute terms
__device__ __forceinline__ float tanh_fast(float x) {
    return fmaf(2.f, sigf(2.f * x), -1.f);
}

// One LSTM layer, NB batch chains per CTA, all T steps.
// Shared: Wt[128][256] (k-major, columns interleaved unit*4+gate), bias[256],
//         xh[128][NB] (rows 0..63 = x_t, rows 64..127 = h_{t-1}).
extern "C" __global__ void __launch_bounds__(NTHR, 1)
lstm_layer(const float* __restrict__ xin,        // [B, T, 64]
           const float* __restrict__ w_ih,       // [256, 64]
           const float* __restrict__ w_hh,       // [256, 64]
           const float* __restrict__ b_ih,       // [256]
           const float* __restrict__ b_hh,       // [256]
           float* __restrict__ hout,             // [B,T,64] if write_full else [B,64]
           int write_full)
{
    extern __shared__ float sm[];
    float* Wt   = sm;                  // 128*256 floats
    float* bias = sm + 128 * 256;      // 256 floats
    float* xh   = bias + 256;          // 128*NB floats

    const int tid = threadIdx.x;
    const int u   = tid & 63;          // hidden unit owned by this thread
    const int grp = tid >> 6;          // 0..3, batch group
    const int col = grp * 4;           // first of 4 batches this thread updates
    const int b0  = blockIdx.x * NB;

    // Load weights: source row = gate*64 + unit; dest column = unit*4 + gate.
    for (int i = tid; i < 256 * 64; i += NTHR) {
        int row = i >> 6, k = i & 63;
        int cc = ((row & 63) << 2) | (row >> 6);
        Wt[k * 256 + cc]        = w_ih[i];
        Wt[(64 + k) * 256 + cc] = w_hh[i];
    }
    bias[tid] = b_ih[tid] + b_hh[tid];

    // h rows start at zero
    for (int i = tid; i < 64 * NB; i += NTHR) xh[64 * NB + i] = 0.f;

    // preload x_0 (transposed into xh rows 0..63)
    {
        const int pb = tid >> 4, pk = (tid & 15) * 4;
        float4 v = *(const float4*)&xin[(size_t)(b0 + pb) * T_STEPS * HID + pk];
        xh[(pk + 0) * NB + pb] = v.x;
        xh[(pk + 1) * NB + pb] = v.y;
        xh[(pk + 2) * NB + pb] = v.z;
        xh[(pk + 3) * NB + pb] = v.w;
    }

    float c[4] = {0.f, 0.f, 0.f, 0.f};
    __syncthreads();

    const float bi = bias[u], bf = bias[64 + u], bg = bias[128 + u], bo = bias[192 + u];

    for (int t = 0; t < T_STEPS; ++t) {
        // Prefetch next x tile into registers (latency hidden under gate loop)
        const int pb = tid >> 4, pk = (tid & 15) * 4;
        float4 xv = make_float4(0.f, 0.f, 0.f, 0.f);
        if (t + 1 < T_STEPS)
            xv = *(const float4*)&xin[(size_t)(b0 + pb) * T_STEPS * HID
                                      + (size_t)(t + 1) * HID + pk];

        ull a_i0 = pack2(bi, bi), a_i1 = a_i0;
        ull a_f0 = pack2(bf, bf), a_f1 = a_f0;
        ull a_g0 = pack2(bg, bg), a_g1 = a_g0;
        ull a_o0 = pack2(bo, bo), a_o1 = a_o0;

        #pragma unroll 8
        for (int k = 0; k < 128; ++k) {
            float4 wv = *(const float4*)&Wt[k * 256 + (u << 2)];   // gates i,f,g,o
            ull w_i = pack2(wv.x, wv.x);
            ull w_f = pack2(wv.y, wv.y);
            ull w_g = pack2(wv.z, wv.z);
            ull w_o = pack2(wv.w, wv.w);
            ull v0 = *(const ull*)&xh[k * NB + col];       // batches col, col+1
            ull v1 = *(const ull*)&xh[k * NB + col + 2];   // batches col+2, col+3
            ffma2(a_i0, w_i, v0); ffma2(a_i1, w_i, v1);
            ffma2(a_f0, w_f, v0); ffma2(a_f1, w_f, v1);
            ffma2(a_g0, w_g, v0); ffma2(a_g1, w_g, v1);
            ffma2(a_o0, w_o, v0); ffma2(a_o1, w_o, v1);
        }
        __syncthreads();   // all reads of xh done; safe to overwrite below

        float gi[4], gf[4], gg[4], go[4];
        unpack2(a_i0, gi[0], gi[1]); unpack2(a_i1, gi[2], gi[3]);
        unpack2(a_f0, gf[0], gf[1]); unpack2(a_f1, gf[2], gf[3]);
        unpack2(a_g0, gg[0], gg[1]); unpack2(a_g1, gg[2], gg[3]);
        unpack2(a_o0, go[0], go[1]); unpack2(a_o1, go[2], go[3]);

        float hval[4];
        #pragma unroll
        for (int j = 0; j < 4; ++j) {
            float iv = sigf(gi[j]);
            float fv = sigf(gf[j]);
            float gv = tanh_fast(gg[j]);
            float ov = sigf(go[j]);
            c[j] = fmaf(fv, c[j], iv * gv);
            float hv = ov * tanh_fast(c[j]);
            xh[(64 + u) * NB + col + j] = hv;
            hval[j] = hv;
        }

        if (write_full) {
            #pragma unroll
            for (int j = 0; j < 4; ++j)
                hout[(size_t)(b0 + col + j) * T_STEPS * HID + (size_t)t * HID + u] = hval[j];
        } else if (t == T_STEPS - 1) {
            #pragma unroll
            for (int j = 0; j < 4; ++j)
                hout[(b0 + col + j) * HID + u] = hval[j];
        }

        if (t + 1 < T_STEPS) {
            xh[(pk + 0) * NB + pb] = xv.x;
            xh[(pk + 1) * NB + pb] = xv.y;
            xh[(pk + 2) * NB + pb] = xv.z;
            xh[(pk + 3) * NB + pb] = xv.w;
        }
        __syncthreads();   // xh (x_{t+1}, h_t) ready for next step
    }
}

// Final FC: out[b][n] = h2[b] . fc_w[n] + fc_b[n]
extern "C" __global__ void fc_kernel(const float* __restrict__ fc_w,
                                     const float* __restrict__ fc_b,
                                     float* __restrict__ out)
{
    int idx = blockIdx.x * blockDim.x + threadIdx.x;   // 8192 = 2048*4
    if (idx >= BATCH * 4) return;
    int b = idx >> 2, n = idx & 3;
    const float* h = &g_h2[b * HID];
    const float* w = &fc_w[n * HID];
    float acc = fc_b[n];
    #pragma unroll
    for (int k = 0; k < HID; ++k) acc = fmaf(h[k], w[k], acc);
    out[idx] = acc;
}

extern "C" void kernel_launch(void* const* d_in, const int* in_sizes, int n_in,
                              void* d_out, int out_size)
{
    const float* x     = (const float*)d_in[0];
    const float* w_ih0 = (const float*)d_in[1];
    const float* w_hh0 = (const float*)d_in[2];
    const float* b_ih0 = (const float*)d_in[3];
    const float* b_hh0 = (const float*)d_in[4];
    const float* w_ih1 = (const float*)d_in[5];
    const float* w_hh1 = (const float*)d_in[6];
    const float* b_ih1 = (const float*)d_in[7];
    const float* b_hh1 = (const float*)d_in[8];
    const float* fc_w  = (const float*)d_in[9];
    const float* fc_b  = (const float*)d_in[10];
    float* out = (float*)d_out;

    const size_t smem = (size_t)(128 * 256 + 256 + 128 * NB) * sizeof(float);
    cudaFuncSetAttribute(lstm_layer, cudaFuncAttributeMaxDynamicSharedMemorySize, (int)smem);

    float *h1, *h2;
    cudaGetSymbolAddress((void**)&h1, g_h1);
    cudaGetSymbolAddress((void**)&h2, g_h2);

    lstm_layer<<<BATCH / NB, NTHR, smem>>>(x,  w_ih0, w_hh0, b_ih0, b_hh0, h1, 1);
    lstm_layer<<<BATCH / NB, NTHR, smem>>>(h1, w_ih1, w_hh1, b_ih1, b_hh1, h2, 0);
    fc_kernel<<<(BATCH * 4 + 255) / 256, 256>>>(fc_w, fc_b, out);
}

// round 3
// speedup vs baseline: 1.0170x; 1.0170x over previous
#include <cuda_runtime.h>

#define T_STEPS 512
#define HID     64
#define BATCH   2048
#define NB      16
#define NTHR    256
#define NC      4

// Inter-layer scratch: full h1 sequence [B, T, H] fp32 (256 MB).
__device__ float g_h1[(size_t)BATCH * T_STEPS * HID];

typedef unsigned long long ull;

__device__ __forceinline__ ull pack2(float a, float b) {
    ull r; asm("mov.b64 %0, {%1,%2};" : "=l"(r) : "f"(a), "f"(b)); return r;
}
__device__ __forceinline__ void ffma2(ull &acc, ull a, ull b) {
    asm("fma.rn.f32x2 %0, %1, %2, %0;" : "+l"(acc) : "l"(a), "l"(b));
}
__device__ __forceinline__ void unpack2(ull v, float &lo, float &hi) {
    asm("mov.b64 {%0,%1}, %2;" : "=f"(lo), "=f"(hi) : "l"(v));
}

__device__ __forceinline__ float sigf(float x) {
    return __fdividef(1.f, 1.f + __expf(-x));
}
__device__ __forceinline__ float tanh_fast(float x) {
    return fmaf(2.f, sigf(2.f * x), -1.f);
}

// Fused 2-layer LSTM + FC. One CTA owns NB=16 batch chains end-to-end.
// Shared: Wt[128][256] (k-major, column = unit*4 + gate), bias[256] (COLUMN order),
//         xh[128][16] (rows 0..63 = x_t transposed, rows 64..127 = h_{t-1} transposed).
// Warp tiling: warp w -> (cg = w>>1: 64 gate-columns, p = w&1: 8 batches).
// Lane owns columns c0 = cg*64 + 2*lane, c0+1 (gate pair (i,f) or (g,o) of unit c0>>2)
// and all 8 batches p*8 .. p*8+7 in the k-loop; after the shfl exchange it owns
// all 4 gates of unit c0>>2 for 4 batches.
extern "C" __global__ void __launch_bounds__(NTHR, 1)
lstm2_fused(const float* __restrict__ xin0,      // [B, T, 64]
            const float* __restrict__ w_ih0, const float* __restrict__ w_hh0,
            const float* __restrict__ b_ih0, const float* __restrict__ b_hh0,
            const float* __restrict__ w_ih1, const float* __restrict__ w_hh1,
            const float* __restrict__ b_ih1, const float* __restrict__ b_hh1,
            const float* __restrict__ fc_w,  const float* __restrict__ fc_b,
            float* __restrict__ h1buf,             // [B, T, 64] scratch
            float* __restrict__ out)               // [B, 4]
{
    extern __shared__ float sm[];
    float* Wt   = sm;                  // 128*256
    float* bias = sm + 128 * 256;      // 256  (column layout: unit*4 + gate)
    float* xh   = bias + 256;          // 128*16

    const int tid  = threadIdx.x;
    const int lane = tid & 31;
    const int wid  = tid >> 5;
    const int p    = wid & 1;          // batch half: batches p*8 .. p*8+7
    const int cg   = wid >> 1;         // column group (64 columns)
    const int c0   = cg * 64 + 2 * lane;
    const int u    = c0 >> 2;          // hidden unit owned (with lane^1 partner)
    const int od   = lane & 1;         // 0: gates (i,f)   1: gates (g,o)
    const int p8   = p * 8;
    const int bb   = p8 + (od ? 4 : 0);// this lane's 4 activation batches
    const int b0   = blockIdx.x * NB;

    // x-prefetch mapping (all 256 threads): pb = batch, pk = 4 units
    const int pb = tid >> 4, pk = (tid & 15) * 4;

    for (int layer = 0; layer < 2; ++layer) {
        const float* xin  = layer ? h1buf : xin0;
        const float* w_ih = layer ? w_ih1 : w_ih0;
        const float* w_hh = layer ? w_hh1 : w_hh0;
        const float* b_ih = layer ? b_ih1 : b_ih0;
        const float* b_hh = layer ? b_hh1 : b_hh0;

        __syncthreads();   // previous layer fully done with Wt/xh

        // Load weights: src row r = gate*64 + unit  ->  column (unit*4 + gate)
        for (int i = tid; i < 256 * 64; i += NTHR) {
            int row = i >> 6, kk = i & 63;
            int cc = ((row & 63) << 2) | (row >> 6);
            Wt[kk * 256 + cc]        = w_ih[i];
            Wt[(64 + kk) * 256 + cc] = w_hh[i];
        }
        // Bias in COLUMN layout (fix for R2: was stored row-order, read column-order)
        {
            int cc = ((tid & 63) << 2) | (tid >> 6);
            bias[cc] = b_ih[tid] + b_hh[tid];
        }

        // zero h rows
        for (int i = tid; i < 64 * 16; i += NTHR) xh[64 * 16 + i] = 0.f;

        // preload x_0 transposed
        {
            float4 v = *(const float4*)&xin[(size_t)(b0 + pb) * T_STEPS * HID + pk];
            xh[(pk + 0) * 16 + pb] = v.x;
            xh[(pk + 1) * 16 + pb] = v.y;
            xh[(pk + 2) * 16 + pb] = v.z;
            xh[(pk + 3) * 16 + pb] = v.w;
        }
        __syncthreads();

        const float bia = bias[c0], bib = bias[c0 + 1];
        float c[4] = {0.f, 0.f, 0.f, 0.f};

        const float2* wp = (const float2*)Wt;     // row stride 128 float2
        const int wofs = cg * 32 + lane;          // (c0>>1) within row

        for (int t = 0; t < T_STEPS; ++t) {
            // prefetch next x tile into registers
            float4 xv = make_float4(0.f, 0.f, 0.f, 0.f);
            if (t + 1 < T_STEPS)
                xv = *(const float4*)&xin[(size_t)(b0 + pb) * T_STEPS * HID
                                          + (size_t)(t + 1) * HID + pk];

            ull A00 = pack2(bia, bia), A01 = A00, A02 = A00, A03 = A00;
            ull A10 = pack2(bib, bib), A11 = A10, A12 = A10, A13 = A10;

            #pragma unroll 8
            for (int k = 0; k < 128; ++k) {
                float2 w = wp[k * 128 + wofs];
                ulonglong2 va = *(const ulonglong2*)&xh[k * 16 + p8];      // b0..b3
                ulonglong2 vb = *(const ulonglong2*)&xh[k * 16 + p8 + 4];  // b4..b7
                ull w0 = pack2(w.x, w.x);
                ull w1 = pack2(w.y, w.y);
                ffma2(A00, w0, va.x); ffma2(A01, w0, va.y);
                ffma2(A02, w0, vb.x); ffma2(A03, w0, vb.y);
                ffma2(A10, w1, va.x); ffma2(A11, w1, va.y);
                ffma2(A12, w1, vb.x); ffma2(A13, w1, vb.y);
            }
            __syncthreads();   // all xh reads done

            // Gate exchange with the lane^1 partner (same unit, other gate pair).
            // even lane keeps batches b0..b3, odd lane keeps b4..b7.
            ull sx0 = od ? A00 : A02;   // send: g[b01] / i[b45]
            ull sx1 = od ? A01 : A03;
            ull sx2 = od ? A10 : A12;   // send: o[b01] / f[b45]
            ull sx3 = od ? A11 : A13;
            ull r0 = __shfl_xor_sync(0xffffffffu, sx0, 1);
            ull r1 = __shfl_xor_sync(0xffffffffu, sx1, 1);
            ull r2 = __shfl_xor_sync(0xffffffffu, sx2, 1);
            ull r3 = __shfl_xor_sync(0xffffffffu, sx3, 1);

            ull Ig0 = od ? r0  : A00,  Ig1 = od ? r1  : A01;
            ull Fg0 = od ? r2  : A10,  Fg1 = od ? r3  : A11;
            ull Gg0 = od ? A02 : r0,   Gg1 = od ? A03 : r1;
            ull Og0 = od ? A12 : r2,   Og1 = od ? A13 : r3;

            float gi[4], gf[4], gg[4], go[4];
            unpack2(Ig0, gi[0], gi[1]); unpack2(Ig1, gi[2], gi[3]);
            unpack2(Fg0, gf[0], gf[1]); unpack2(Fg1, gf[2], gf[3]);
            unpack2(Gg0, gg[0], gg[1]); unpack2(Gg1, gg[2], gg[3]);
            unpack2(Og0, go[0], go[1]); unpack2(Og1, go[2], go[3]);

            float hv[4];
            #pragma unroll
            for (int j = 0; j < 4; ++j) {
                float iv = sigf(gi[j]);
                float fv = sigf(gf[j]);
                float gv = tanh_fast(gg[j]);
                float ov = sigf(go[j]);
                c[j] = fmaf(fv, c[j], iv * gv);
                hv[j] = ov * tanh_fast(c[j]);
            }

            // h -> xh rows 64..127 (transposed), one STS.128 per lane
            *(float4*)&xh[(64 + u) * 16 + bb] = make_float4(hv[0], hv[1], hv[2], hv[3]);

            if (layer == 0) {
                #pragma unroll
                for (int j = 0; j < 4; ++j)
                    h1buf[(size_t)(b0 + bb + j) * T_STEPS * HID
                          + (size_t)t * HID + u] = hv[j];
            }

            if (t + 1 < T_STEPS) {
                xh[(pk + 0) * 16 + pb] = xv.x;
                xh[(pk + 1) * 16 + pb] = xv.y;
                xh[(pk + 2) * 16 + pb] = xv.z;
                xh[(pk + 3) * 16 + pb] = xv.w;
            }
            __syncthreads();   // xh (x_{t+1}, h_t) ready
        }
    }

    // Fused FC: xh rows 64..127 hold h2_last (transposed). 64 outputs per CTA.
    if (tid < NB * NC) {
        int b = tid >> 2, n = tid & 3;
        float acc = fc_b[n];
        #pragma unroll
        for (int k = 0; k < HID; ++k)
            acc = fmaf(xh[(64 + k) * 16 + b], fc_w[n * HID + k], acc);
        out[(b0 + b) * NC + n] = acc;
    }
}

extern "C" void kernel_launch(void* const* d_in, const int* in_sizes, int n_in,
                              void* d_out, int out_size)
{
    const float* x     = (const float*)d_in[0];
    const float* w_ih0 = (const float*)d_in[1];
    const float* w_hh0 = (const float*)d_in[2];
    const float* b_ih0 = (const float*)d_in[3];
    const float* b_hh0 = (const float*)d_in[4];
    const float* w_ih1 = (const float*)d_in[5];
    const float* w_hh1 = (const float*)d_in[6];
    const float* b_ih1 = (const float*)d_in[7];
    const float* b_hh1 = (const float*)d_in[8];
    const float* fc_w  = (const float*)d_in[9];
    const float* fc_b  = (const float*)d_in[10];
    float* out = (float*)d_out;

    const size_t smem = (size_t)(128 * 256 + 256 + 128 * 16) * sizeof(float);
    cudaFuncSetAttribute(lstm2_fused, cudaFuncAttributeMaxDynamicSharedMemorySize, (int)smem);

    float* h1;
    cudaGetSymbolAddress((void**)&h1, g_h1);

    lstm2_fused<<<BATCH / NB, NTHR, smem>>>(x,
        w_ih0, w_hh0, b_ih0, b_hh0,
        w_ih1, w_hh1, b_ih1, b_hh1,
        fc_w, fc_b, h1, out);
}